// round 16
// baseline (speedup 1.0000x reference)
#include <cuda_runtime.h>
#include <cuda_fp16.h>
#include <cstdint>

// ---------------- problem constants ----------------
#define BSZ   16
#define SEQ   1024
#define DIM   768
#define NH    12
#define HDIM  64
#define PLEN  16
#define KEYS  (PLEN + SEQ)       // 1040
#define FFD   (4 * DIM)          // 3072
#define ROWS  (BSZ * SEQ)        // 16384

// ---------------- scratch (device globals: no alloc allowed) ----------------
__device__ __half g_h   [(size_t)ROWS * DIM];
__device__ __half g_qkv [(size_t)ROWS * 3 * DIM];
__device__ __half g_attn[(size_t)ROWS * DIM];
__device__ float  g_xr  [(size_t)ROWS * DIM];
__device__ __half g_ff  [(size_t)ROWS * FFD];
__device__ __half g_w   [(size_t)(3 * DIM + DIM + FFD + DIM) * DIM * 4];

#define WQ_OFF  0
#define WO_OFF  ((size_t)3 * DIM * DIM)
#define WF1_OFF (WO_OFF + (size_t)DIM * DIM)
#define WF2_OFF (WF1_OFF + (size_t)FFD * DIM)
#define WTOTAL  (WF2_OFF + (size_t)DIM * FFD)

// ---------------- helpers ----------------
__device__ __forceinline__ uint32_t smem_u32(const void* p) {
    uint32_t a;
    asm("{ .reg .u64 t; cvta.to.shared.u64 t, %1; cvt.u32.u64 %0, t; }" : "=r"(a) : "l"(p));
    return a;
}
__device__ __forceinline__ float ex2f(float x) {
    float r;
    asm("ex2.approx.f32 %0, %1;" : "=f"(r) : "f"(x));
    return r;
}
__device__ __forceinline__ void cp_async16(uint32_t dst, const void* src) {
    asm volatile("cp.async.cg.shared.global [%0], [%1], 16;" :: "r"(dst), "l"(src) : "memory");
}
__device__ __forceinline__ void cp_async16_z(uint32_t dst, const void* src, int sz) {
    asm volatile("cp.async.cg.shared.global [%0], [%1], 16, %2;" :: "r"(dst), "l"(src), "r"(sz) : "memory");
}
#define CP_COMMIT() asm volatile("cp.async.commit_group;" ::: "memory")
#define CP_WAIT(n)  asm volatile("cp.async.wait_group %0;" :: "n"(n) : "memory")

__device__ __forceinline__ void ldsm_x4(uint32_t* r, uint32_t addr) {
    asm volatile("ldmatrix.sync.aligned.m8n8.x4.shared.b16 {%0,%1,%2,%3}, [%4];"
        : "=r"(r[0]), "=r"(r[1]), "=r"(r[2]), "=r"(r[3]) : "r"(addr));
}
__device__ __forceinline__ void ldsm_x4_t(uint32_t* r, uint32_t addr) {
    asm volatile("ldmatrix.sync.aligned.m8n8.x4.trans.shared.b16 {%0,%1,%2,%3}, [%4];"
        : "=r"(r[0]), "=r"(r[1]), "=r"(r[2]), "=r"(r[3]) : "r"(addr));
}
__device__ __forceinline__ void mma_f16(float* c, const uint32_t* a, const uint32_t* b) {
    asm volatile(
        "mma.sync.aligned.m16n8k16.row.col.f32.f16.f16.f32 "
        "{%0,%1,%2,%3}, {%4,%5,%6,%7}, {%8,%9}, {%0,%1,%2,%3};"
        : "+f"(c[0]), "+f"(c[1]), "+f"(c[2]), "+f"(c[3])
        : "r"(a[0]), "r"(a[1]), "r"(a[2]), "r"(a[3]), "r"(b[0]), "r"(b[1]));
}

// ---------------- weight convert (float4 vectorized, single launch) ----------------
__global__ void cvt_w_all(const float* __restrict__ qkv_w, const float* __restrict__ out_w,
                          const float* __restrict__ fc1_w, const float* __restrict__ fc2_w,
                          __half* __restrict__ out) {
    size_t i4 = ((size_t)blockIdx.x * 256 + threadIdx.x) * 4;
    if (i4 >= WTOTAL) return;
    const float* src;
    if (i4 < WO_OFF)        src = qkv_w + i4;
    else if (i4 < WF1_OFF)  src = out_w + (i4 - WO_OFF);
    else if (i4 < WF2_OFF)  src = fc1_w + (i4 - WF1_OFF);
    else                    src = fc2_w + (i4 - WF2_OFF);
    float4 v = *(const float4*)src;
    __half2 h0 = __floats2half2_rn(v.x, v.y);
    __half2 h1 = __floats2half2_rn(v.z, v.w);
    uint2 o = make_uint2(*(uint32_t*)&h0, *(uint32_t*)&h1);
    *(uint2*)(out + i4) = o;
}

// ---------------- fp16 mma.sync GEMM: 128x128, 8 warps 64x32, single-barrier 3-stage ----
#define GBUFB     18432
#define ABUF(s)   ((s) * GBUFB)
#define BBUF(s)   (3 * GBUFB + (s) * GBUFB)
#define GSM_BYTES (6 * GBUFB)

__global__ void __launch_bounds__(256, 2)
mma_gemm(const __half* __restrict__ A, const __half* __restrict__ W,
         const float* __restrict__ bias, const float* __restrict__ resid,
         void* __restrict__ Cout, int M, int N, int K, int mode) {
    extern __shared__ char smc[];
    uint32_t sb = smem_u32(smc);
    int tid = threadIdx.x;
    int wid = tid >> 5, lane = tid & 31;
    int g = lane >> 2, t = lane & 3;
    int bm = blockIdx.y, bn = blockIdx.x;
    int wm0 = (wid & 1) * 64, wn0 = (wid >> 1) * 32;

    uint32_t a_off = (uint32_t)((wm0 + (lane & 15)) * 144 + ((lane >> 4) * 8) * 2);
    uint32_t b_off = (uint32_t)((wn0 + ((lane >> 4) << 3) + (lane & 7)) * 144 + (((lane >> 3) & 1) * 8) * 2);

    int r  = tid >> 1;
    int hh = (tid & 1) << 5;
    const __half* Ap = A + (size_t)(bm * 128 + r) * K + hh;
    const __half* Wp = W + (size_t)(bn * 128 + r) * K + hh;
    uint32_t smA_dst[3], smB_dst[3];
    #pragma unroll
    for (int s = 0; s < 3; s++) {
        smA_dst[s] = sb + ABUF(s) + r * 144 + hh * 2;
        smB_dst[s] = sb + BBUF(s) + r * 144 + hh * 2;
    }

    float acc[4][4][4] = {};
    int nc = K >> 6;

    #pragma unroll
    for (int i = 0; i < 4; i++) cp_async16(smA_dst[0] + i * 16, Ap + i * 8);
    #pragma unroll
    for (int i = 0; i < 4; i++) cp_async16(smB_dst[0] + i * 16, Wp + i * 8);
    CP_COMMIT();
    #pragma unroll
    for (int i = 0; i < 4; i++) cp_async16(smA_dst[1] + i * 16, Ap + 64 + i * 8);
    #pragma unroll
    for (int i = 0; i < 4; i++) cp_async16(smB_dst[1] + i * 16, Wp + 64 + i * 8);
    CP_COMMIT();

    for (int c = 0; c < nc; c++) {
        int s = c % 3;
        if (c + 1 < nc) { CP_WAIT(1); } else { CP_WAIT(0); }
        __syncthreads();
        if (c + 2 < nc) {
            int s2 = (c + 2) % 3;
            const __half* ap = Ap + (c + 2) * 64;
            const __half* wp = Wp + (c + 2) * 64;
            #pragma unroll
            for (int i = 0; i < 4; i++) cp_async16(smA_dst[s2] + i * 16, ap + i * 8);
            #pragma unroll
            for (int i = 0; i < 4; i++) cp_async16(smB_dst[s2] + i * 16, wp + i * 8);
            CP_COMMIT();
        }

        uint32_t Ab = sb + ABUF(s) + a_off;
        uint32_t Bb = sb + BBUF(s) + b_off;
        #pragma unroll
        for (int k0 = 0; k0 < 64; k0 += 16) {
            uint32_t af[4][4], bf[2][4];
            #pragma unroll
            for (int mt = 0; mt < 4; mt++) ldsm_x4(af[mt], Ab + mt * 2304 + k0 * 2);
            ldsm_x4(bf[0], Bb + k0 * 2);
            ldsm_x4(bf[1], Bb + 2304 + k0 * 2);
            #pragma unroll
            for (int mt = 0; mt < 4; mt++)
                #pragma unroll
                for (int nt = 0; nt < 4; nt++)
                    mma_f16(acc[mt][nt], af[mt], &bf[nt >> 1][(nt & 1) * 2]);
        }
    }

    #pragma unroll
    for (int mt = 0; mt < 4; mt++) {
        #pragma unroll
        for (int half_ = 0; half_ < 2; half_++) {
            int row = bm * 128 + wm0 + mt * 16 + g + half_ * 8;
            #pragma unroll
            for (int nt = 0; nt < 4; nt++) {
                int col = bn * 128 + wn0 + nt * 8 + 2 * t;
                float2 bv = *(const float2*)(bias + col);
                float vx = acc[mt][nt][2 * half_ + 0] + bv.x;
                float vy = acc[mt][nt][2 * half_ + 1] + bv.y;
                if (mode == 2) {
                    float2 rs = *(const float2*)(resid + (size_t)row * N + col);
                    vx += rs.x; vy += rs.y;
                    *(float2*)((float*)Cout + (size_t)row * N + col) = make_float2(vx, vy);
                } else {
                    if (mode == 1) {
                        vx *= 1.f / (1.f + __expf(-1.702f * vx));
                        vy *= 1.f / (1.f + __expf(-1.702f * vy));
                    }
                    __half* Co = (__half*)Cout + (size_t)row * N;
                    *(__half2*)(Co + col) = __floats2half2_rn(vx, vy);
                }
            }
        }
    }
}

// ---------------- LayerNorm: warp-per-row, 8 rows/block, shfl-only ----------------
__global__ void ln_kernel(const float* __restrict__ x, const float* __restrict__ g,
                          const float* __restrict__ b, __half* __restrict__ out) {
    int wid = threadIdx.x >> 5, lane = threadIdx.x & 31;
    int row = blockIdx.x * 8 + wid;
    const float* xr = x + (size_t)row * DIM;

    float4 v[6];
    float s = 0.f, ss = 0.f;
    #pragma unroll
    for (int j = 0; j < 6; j++) {
        v[j] = *(const float4*)(xr + (j * 32 + lane) * 4);
        s  += v[j].x + v[j].y + v[j].z + v[j].w;
        ss += v[j].x * v[j].x + v[j].y * v[j].y + v[j].z * v[j].z + v[j].w * v[j].w;
    }
    #pragma unroll
    for (int o = 16; o > 0; o >>= 1) {
        s  += __shfl_xor_sync(0xffffffffu, s, o);
        ss += __shfl_xor_sync(0xffffffffu, ss, o);
    }
    float mean = s * (1.f / DIM);
    float var  = ss * (1.f / DIM) - mean * mean;
    float rstd = rsqrtf(var + 1e-5f);

    __half* orow = out + (size_t)row * DIM;
    #pragma unroll
    for (int j = 0; j < 6; j++) {
        int idx = (j * 32 + lane) * 4;
        float4 gv = *(const float4*)(g + idx);
        float4 bv = *(const float4*)(b + idx);
        __half2 h0 = __floats2half2_rn((v[j].x - mean) * rstd * gv.x + bv.x,
                                       (v[j].y - mean) * rstd * gv.y + bv.y);
        __half2 h1 = __floats2half2_rn((v[j].z - mean) * rstd * gv.z + bv.z,
                                       (v[j].w - mean) * rstd * gv.w + bv.w);
        *(uint2*)(orow + idx) = make_uint2(*(uint32_t*)&h0, *(uint32_t*)&h1);
    }
}

// ---------------- FlashAttention-2 (R12 shape): Q hoist, fused softmax/PV, 2-buffer ----
#define FKV(i) (9216 + (i) * 9216)
#define FATT_BYTES ((9216 + 2 * 9216) * 2)  // 55296
#define SM_C 0.18033688f                     // 0.125 * log2(e)

__global__ void __launch_bounds__(256, 2)
attn_kernel(const __half* __restrict__ qkv, const float* __restrict__ prompt,
            __half* __restrict__ out) {
    extern __shared__ __half sh[];
    __half* Qs = sh;

    uint32_t sbase = smem_u32(sh);
    int qt = blockIdx.x, h = blockIdx.y, b = blockIdx.z;
    int tid = threadIdx.x;
    int wid = tid >> 5, lane = tid & 31;
    int g = lane >> 2, t = lane & 3;
    int q0 = wid * 16;

    uint32_t aq_off = (uint32_t)((q0 + (lane & 15)) * 144 + ((lane >> 4) * 8) * 2);
    uint32_t bk_off = (uint32_t)((((lane >> 4) << 3) + (lane & 7)) * 144 + (((lane >> 3) & 1) * 8) * 2);
    uint32_t bv_off = (uint32_t)((lane & 15) * 144 + ((lane >> 4) << 3) * 2);

    // --- Q tile (128 rows) ---
    {
        int q = tid >> 1, ch = tid & 1;
        int n = qt * 128 + q;
        const __half* src = qkv + (size_t)(b * SEQ + n) * (3 * DIM) + h * HDIM + ch * 32;
        *(uint4*)(Qs + q * 72 + ch * 32)      = *(const uint4*)(src);
        *(uint4*)(Qs + q * 72 + ch * 32 + 8)  = *(const uint4*)(src + 8);
        *(uint4*)(Qs + q * 72 + ch * 32 + 16) = *(const uint4*)(src + 16);
        *(uint4*)(Qs + q * 72 + ch * 32 + 24) = *(const uint4*)(src + 24);
    }

    // --- tile 0 K/V: synchronous fill into buf 0 (handles prompt conversion) ---
    {
        int key = tid & 63, ch = tid >> 6;
        int tensor = ch >> 1, c2 = ch & 1;
        __half* dst = sh + FKV(0) + tensor * 4608 + key * 72 + c2 * 32;
        if (key >= PLEN) {
            const __half* src = qkv + (size_t)(b * SEQ + (key - PLEN)) * (3 * DIM)
                                + (1 + tensor) * DIM + h * HDIM + c2 * 32;
            *(uint4*)(dst)      = *(const uint4*)(src);
            *(uint4*)(dst + 8)  = *(const uint4*)(src + 8);
            *(uint4*)(dst + 16) = *(const uint4*)(src + 16);
            *(uint4*)(dst + 24) = *(const uint4*)(src + 24);
        } else {
            const float* src = prompt + ((((size_t)b * 2 + tensor) * PLEN + key) * NH + h) * HDIM + c2 * 32;
            #pragma unroll
            for (int ii = 0; ii < 16; ii++) {
                float2 v = *(const float2*)(src + ii * 2);
                *(__half2*)(dst + ii * 2) = __floats2half2_rn(v.x, v.y);
            }
        }
    }
    __syncthreads();                      // Q + tile0 K/V visible

    // --- hoist Q fragments (loop-invariant): 16 regs ---
    uint32_t qf[4][4];
    #pragma unroll
    for (int i = 0; i < 4; i++) ldsm_x4(qf[i], sbase + aq_off + i * 32);

    float m0 = -1e30f, m1 = -1e30f, l0 = 0.f, l1 = 0.f;   // m in log2-scaled domain
    float acc_o[8][4] = {};

    int pkey = tid & 63, pch = tid >> 6;
    int ptensor = pch >> 1, pc2 = pch & 1;

    // ================= main loop: tiles 0..15, no masking =================
    for (int kt = 0; kt < 16; kt++) {
        int bb = kt & 1;
        if (kt >= 1) { CP_WAIT(0); __syncthreads(); }

        {   // prefetch tile kt+1 (zfill covers the tile-16 tail)
            int kg = (kt + 1) * 64 + pkey;
            int kgc = kg < KEYS ? kg : KEYS - 1;
            int sz = kg < KEYS ? 16 : 0;
            const __half* src = qkv + (size_t)(b * SEQ + (kgc - PLEN)) * (3 * DIM)
                                + (1 + ptensor) * DIM + h * HDIM + pc2 * 32;
            uint32_t dst = sbase + (uint32_t)(FKV(bb ^ 1) + ptensor * 4608 + pkey * 72 + pc2 * 32) * 2;
            #pragma unroll
            for (int i = 0; i < 4; i++) cp_async16_z(dst + i * 16, src + i * 8, sz);
            CP_COMMIT();
        }

        uint32_t kbase_b = sbase + (uint32_t)FKV(bb) * 2;
        uint32_t vbase_b = kbase_b + 4608 * 2;

        // --- S = Q @ K^T ---
        float s4[8][4] = {};
        #pragma unroll
        for (int k0i = 0; k0i < 4; k0i++) {
            uint32_t bf[4][4];
            #pragma unroll
            for (int j = 0; j < 4; j++)
                ldsm_x4(bf[j], kbase_b + bk_off + j * 16 * 144 + k0i * 32);
            #pragma unroll
            for (int nt = 0; nt < 8; nt++)
                mma_f16(s4[nt], qf[k0i], &bf[nt >> 1][(nt & 1) * 2]);
        }

        // --- softmax pass A: max / rescale ---
        float tm0 = -1e30f, tm1 = -1e30f;
        #pragma unroll
        for (int nt = 0; nt < 8; nt++) {
            tm0 = fmaxf(tm0, fmaxf(s4[nt][0], s4[nt][1]));
            tm1 = fmaxf(tm1, fmaxf(s4[nt][2], s4[nt][3]));
        }
        tm0 = fmaxf(tm0, __shfl_xor_sync(0xffffffffu, tm0, 1));
        tm0 = fmaxf(tm0, __shfl_xor_sync(0xffffffffu, tm0, 2));
        tm1 = fmaxf(tm1, __shfl_xor_sync(0xffffffffu, tm1, 1));
        tm1 = fmaxf(tm1, __shfl_xor_sync(0xffffffffu, tm1, 2));
        float mn0 = fmaxf(m0, tm0 * SM_C);
        float mn1 = fmaxf(m1, tm1 * SM_C);
        float a0 = ex2f(m0 - mn0), a1 = ex2f(m1 - mn1);
        m0 = mn0; m1 = mn1;
        #pragma unroll
        for (int nt = 0; nt < 8; nt++) {
            acc_o[nt][0] *= a0; acc_o[nt][1] *= a0;
            acc_o[nt][2] *= a1; acc_o[nt][3] *= a1;
        }

        // --- pass B: per 16-key chunk, P-halves + PV immediately ---
        float ls0 = 0.f, ls1 = 0.f;
        #pragma unroll
        for (int j = 0; j < 4; j++) {
            uint32_t af[4];
            #pragma unroll
            for (int u = 0; u < 2; u++) {
                int nt = 2 * j + u;
                float p0 = ex2f(fmaf(s4[nt][0], SM_C, -mn0));
                float p1 = ex2f(fmaf(s4[nt][1], SM_C, -mn0));
                float p2 = ex2f(fmaf(s4[nt][2], SM_C, -mn1));
                float p3 = ex2f(fmaf(s4[nt][3], SM_C, -mn1));
                ls0 += p0 + p1; ls1 += p2 + p3;
                __half2 h01 = __floats2half2_rn(p0, p1);
                __half2 h23 = __floats2half2_rn(p2, p3);
                af[2 * u + 0] = *(uint32_t*)&h01;
                af[2 * u + 1] = *(uint32_t*)&h23;
            }
            uint32_t bf[4][4];
            #pragma unroll
            for (int dj = 0; dj < 4; dj++)
                ldsm_x4_t(bf[dj], vbase_b + bv_off + j * 16 * 144 + dj * 16 * 2);
            #pragma unroll
            for (int nt = 0; nt < 8; nt++)
                mma_f16(acc_o[nt], af, &bf[nt >> 1][(nt & 1) * 2]);
        }
        ls0 += __shfl_xor_sync(0xffffffffu, ls0, 1);
        ls0 += __shfl_xor_sync(0xffffffffu, ls0, 2);
        ls1 += __shfl_xor_sync(0xffffffffu, ls1, 1);
        ls1 += __shfl_xor_sync(0xffffffffu, ls1, 2);
        l0 = l0 * a0 + ls0;
        l1 = l1 * a1 + ls1;
    }

    // ================= last tile (kt=16): keys 1024..1039, quarter work =================
    {
        CP_WAIT(0);
        __syncthreads();
        uint32_t kbase_b = sbase + (uint32_t)FKV(0) * 2;   // 16 & 1 == 0
        uint32_t vbase_b = kbase_b + 4608 * 2;

        float s4[2][4] = {};
        #pragma unroll
        for (int k0i = 0; k0i < 4; k0i++) {
            uint32_t bf[4];
            ldsm_x4(bf, kbase_b + bk_off + k0i * 32);
            mma_f16(s4[0], qf[k0i], &bf[0]);
            mma_f16(s4[1], qf[k0i], &bf[2]);
        }
        float tm0 = fmaxf(fmaxf(s4[0][0], s4[0][1]), fmaxf(s4[1][0], s4[1][1]));
        float tm1 = fmaxf(fmaxf(s4[0][2], s4[0][3]), fmaxf(s4[1][2], s4[1][3]));
        tm0 = fmaxf(tm0, __shfl_xor_sync(0xffffffffu, tm0, 1));
        tm0 = fmaxf(tm0, __shfl_xor_sync(0xffffffffu, tm0, 2));
        tm1 = fmaxf(tm1, __shfl_xor_sync(0xffffffffu, tm1, 1));
        tm1 = fmaxf(tm1, __shfl_xor_sync(0xffffffffu, tm1, 2));
        float mn0 = fmaxf(m0, tm0 * SM_C);
        float mn1 = fmaxf(m1, tm1 * SM_C);
        float a0 = ex2f(m0 - mn0), a1 = ex2f(m1 - mn1);
        #pragma unroll
        for (int nt = 0; nt < 8; nt++) {
            acc_o[nt][0] *= a0; acc_o[nt][1] *= a0;
            acc_o[nt][2] *= a1; acc_o[nt][3] *= a1;
        }

        float ls0 = 0.f, ls1 = 0.f;
        uint32_t af[4];
        #pragma unroll
        for (int u = 0; u < 2; u++) {
            float p0 = ex2f(fmaf(s4[u][0], SM_C, -mn0));
            float p1 = ex2f(fmaf(s4[u][1], SM_C, -mn0));
            float p2 = ex2f(fmaf(s4[u][2], SM_C, -mn1));
            float p3 = ex2f(fmaf(s4[u][3], SM_C, -mn1));
            ls0 += p0 + p1; ls1 += p2 + p3;
            __half2 h01 = __floats2half2_rn(p0, p1);
            __half2 h23 = __floats2half2_rn(p2, p3);
            af[2 * u + 0] = *(uint32_t*)&h01;
            af[2 * u + 1] = *(uint32_t*)&h23;
        }
        uint32_t bf[4][4];
        #pragma unroll
        for (int dj = 0; dj < 4; dj++)
            ldsm_x4_t(bf[dj], vbase_b + bv_off + dj * 16 * 2);
        #pragma unroll
        for (int nt = 0; nt < 8; nt++)
            mma_f16(acc_o[nt], af, &bf[nt >> 1][(nt & 1) * 2]);

        ls0 += __shfl_xor_sync(0xffffffffu, ls0, 1);
        ls0 += __shfl_xor_sync(0xffffffffu, ls0, 2);
        ls1 += __shfl_xor_sync(0xffffffffu, ls1, 1);
        ls1 += __shfl_xor_sync(0xffffffffu, ls1, 2);
        l0 = l0 * a0 + ls0;
        l1 = l1 * a1 + ls1;
    }

    // --- finalize ---
    float li0 = 1.f / l0, li1 = 1.f / l1;
    int nrow0 = qt * 128 + q0 + g;
    __half* o0 = out + (size_t)(b * SEQ + nrow0) * DIM + h * HDIM;
    __half* o1 = out + (size_t)(b * SEQ + nrow0 + 8) * DIM + h * HDIM;
    #pragma unroll
    for (int nt = 0; nt < 8; nt++) {
        int col = nt * 8 + 2 * t;
        *(__half2*)(o0 + col) = __floats2half2_rn(acc_o[nt][0] * li0, acc_o[nt][1] * li0);
        *(__half2*)(o1 + col) = __floats2half2_rn(acc_o[nt][2] * li1, acc_o[nt][3] * li1);
    }
}

// ---------------- launch ----------------
extern "C" void kernel_launch(void* const* d_in, const int* in_sizes, int n_in,
                              void* d_out, int out_size) {
    const float* x      = (const float*)d_in[0];
    const float* prompt = (const float*)d_in[1];
    const float* qkv_w  = (const float*)d_in[2];
    const float* qkv_b  = (const float*)d_in[3];
    const float* out_w  = (const float*)d_in[4];
    const float* out_b  = (const float*)d_in[5];
    const float* ln1_g  = (const float*)d_in[6];
    const float* ln1_b  = (const float*)d_in[7];
    const float* ln2_g  = (const float*)d_in[8];
    const float* ln2_b  = (const float*)d_in[9];
    const float* fc1_w  = (const float*)d_in[10];
    const float* fc1_b  = (const float*)d_in[11];
    const float* fc2_w  = (const float*)d_in[12];
    const float* fc2_b  = (const float*)d_in[13];
    float* out = (float*)d_out;

    __half *h, *qkv, *attn, *ff, *w;
    float *xr;
    cudaGetSymbolAddress((void**)&h,    g_h);
    cudaGetSymbolAddress((void**)&qkv,  g_qkv);
    cudaGetSymbolAddress((void**)&attn, g_attn);
    cudaGetSymbolAddress((void**)&xr,   g_xr);
    cudaGetSymbolAddress((void**)&ff,   g_ff);
    cudaGetSymbolAddress((void**)&w,    g_w);

    __half* wq  = w + WQ_OFF;
    __half* wo  = w + WO_OFF;
    __half* wf1 = w + WF1_OFF;
    __half* wf2 = w + WF2_OFF;

    cudaFuncSetAttribute(attn_kernel, cudaFuncAttributeMaxDynamicSharedMemorySize, FATT_BYTES);
    cudaFuncSetAttribute(mma_gemm, cudaFuncAttributeMaxDynamicSharedMemorySize, GSM_BYTES);

    // 0) weights -> fp16
    cvt_w_all<<<(int)((WTOTAL / 4 + 255) / 256), 256>>>(qkv_w, out_w, fc1_w, fc2_w, w);

    // 1) h = LN1(x)
    ln_kernel<<<ROWS / 8, 256>>>(x, ln1_g, ln1_b, h);
    // 2) qkv = h @ qkv_w^T + qkv_b
    mma_gemm<<<dim3(3 * DIM / 128, ROWS / 128), 256, GSM_BYTES>>>(h, wq, qkv_b, nullptr, qkv,
                                                                  ROWS, 3 * DIM, DIM, 0);
    // 3) attention
    attn_kernel<<<dim3(SEQ / 128, NH, BSZ), 256, FATT_BYTES>>>(qkv, prompt, attn);
    // 4) xr = x + attn @ out_w^T + out_b
    mma_gemm<<<dim3(DIM / 128, ROWS / 128), 256, GSM_BYTES>>>(attn, wo, out_b, x, xr,
                                                              ROWS, DIM, DIM, 2);
    // 5) h = LN2(xr)
    ln_kernel<<<ROWS / 8, 256>>>(xr, ln2_g, ln2_b, h);
    // 6) ff = quickgelu(h @ fc1_w^T + fc1_b)
    mma_gemm<<<dim3(FFD / 128, ROWS / 128), 256, GSM_BYTES>>>(h, wf1, fc1_b, nullptr, ff,
                                                              ROWS, FFD, DIM, 1);
    // 7) out = xr + ff @ fc2_w^T + fc2_b
    mma_gemm<<<dim3(DIM / 128, ROWS / 128), 256, GSM_BYTES>>>(ff, wf2, fc2_b, xr, out,
                                                              ROWS, DIM, FFD, 2);
}

// round 17
// speedup vs baseline: 1.5479x; 1.5479x over previous
#include <cuda_runtime.h>
#include <cuda_fp16.h>
#include <cstdint>

// ---------------- problem constants ----------------
#define BSZ   16
#define SEQ   1024
#define DIM   768
#define NH    12
#define HDIM  64
#define PLEN  16
#define KEYS  (PLEN + SEQ)       // 1040
#define FFD   (4 * DIM)          // 3072
#define ROWS  (BSZ * SEQ)        // 16384

// ---------------- scratch (device globals: no alloc allowed) ----------------
__device__ __half g_h   [(size_t)ROWS * DIM];
__device__ __half g_qkv [(size_t)ROWS * 3 * DIM];
__device__ __half g_attn[(size_t)ROWS * DIM];
__device__ float  g_xr  [(size_t)ROWS * DIM];
__device__ __half g_ff  [(size_t)ROWS * FFD];
__device__ __half g_w   [(size_t)(3 * DIM + DIM + FFD + DIM) * DIM * 4];

#define WQ_OFF  0
#define WO_OFF  ((size_t)3 * DIM * DIM)
#define WF1_OFF (WO_OFF + (size_t)DIM * DIM)
#define WF2_OFF (WF1_OFF + (size_t)FFD * DIM)
#define WTOTAL  (WF2_OFF + (size_t)DIM * FFD)

// ---------------- helpers ----------------
__device__ __forceinline__ uint32_t smem_u32(const void* p) {
    uint32_t a;
    asm("{ .reg .u64 t; cvta.to.shared.u64 t, %1; cvt.u32.u64 %0, t; }" : "=r"(a) : "l"(p));
    return a;
}
__device__ __forceinline__ float ex2f(float x) {
    float r;
    asm("ex2.approx.f32 %0, %1;" : "=f"(r) : "f"(x));
    return r;
}
__device__ __forceinline__ void cp_async16(uint32_t dst, const void* src) {
    asm volatile("cp.async.cg.shared.global [%0], [%1], 16;" :: "r"(dst), "l"(src) : "memory");
}
__device__ __forceinline__ void cp_async16_z(uint32_t dst, const void* src, int sz) {
    asm volatile("cp.async.cg.shared.global [%0], [%1], 16, %2;" :: "r"(dst), "l"(src), "r"(sz) : "memory");
}
#define CP_COMMIT() asm volatile("cp.async.commit_group;" ::: "memory")
#define CP_WAIT(n)  asm volatile("cp.async.wait_group %0;" :: "n"(n) : "memory")

__device__ __forceinline__ void ldsm_x4(uint32_t* r, uint32_t addr) {
    asm volatile("ldmatrix.sync.aligned.m8n8.x4.shared.b16 {%0,%1,%2,%3}, [%4];"
        : "=r"(r[0]), "=r"(r[1]), "=r"(r[2]), "=r"(r[3]) : "r"(addr));
}
__device__ __forceinline__ void ldsm_x4_t(uint32_t* r, uint32_t addr) {
    asm volatile("ldmatrix.sync.aligned.m8n8.x4.trans.shared.b16 {%0,%1,%2,%3}, [%4];"
        : "=r"(r[0]), "=r"(r[1]), "=r"(r[2]), "=r"(r[3]) : "r"(addr));
}
__device__ __forceinline__ void mma_f16(float* c, const uint32_t* a, const uint32_t* b) {
    asm volatile(
        "mma.sync.aligned.m16n8k16.row.col.f32.f16.f16.f32 "
        "{%0,%1,%2,%3}, {%4,%5,%6,%7}, {%8,%9}, {%0,%1,%2,%3};"
        : "+f"(c[0]), "+f"(c[1]), "+f"(c[2]), "+f"(c[3])
        : "r"(a[0]), "r"(a[1]), "r"(a[2]), "r"(a[3]), "r"(b[0]), "r"(b[1]));
}

// QuickGELU: x * sigmoid(1.702 x) with ex2-based sigmoid (== __expf lowering)
#define QG_C (-2.4554669f)   // -1.702 * log2(e)
__device__ __forceinline__ float quickgelu(float x) {
    return x / (1.f + ex2f(x * QG_C));
}

// ---------------- weight convert (float4 vectorized, single launch) ----------------
__global__ void cvt_w_all(const float* __restrict__ qkv_w, const float* __restrict__ out_w,
                          const float* __restrict__ fc1_w, const float* __restrict__ fc2_w,
                          __half* __restrict__ out) {
    size_t i4 = ((size_t)blockIdx.x * 256 + threadIdx.x) * 4;
    if (i4 >= WTOTAL) return;
    const float* src;
    if (i4 < WO_OFF)        src = qkv_w + i4;
    else if (i4 < WF1_OFF)  src = out_w + (i4 - WO_OFF);
    else if (i4 < WF2_OFF)  src = fc1_w + (i4 - WF1_OFF);
    else                    src = fc2_w + (i4 - WF2_OFF);
    float4 v = *(const float4*)src;
    __half2 h0 = __floats2half2_rn(v.x, v.y);
    __half2 h1 = __floats2half2_rn(v.z, v.w);
    uint2 o = make_uint2(*(uint32_t*)&h0, *(uint32_t*)&h1);
    *(uint2*)(out + i4) = o;
}

// ---------------- fp16 mma.sync GEMM: 128x128, 8 warps 64x32, single-barrier 3-stage ----
#define GBUFB     18432
#define ABUF(s)   ((s) * GBUFB)
#define BBUF(s)   (3 * GBUFB + (s) * GBUFB)
#define GSM_BYTES (6 * GBUFB)

__global__ void __launch_bounds__(256, 2)
mma_gemm(const __half* __restrict__ A, const __half* __restrict__ W,
         const float* __restrict__ bias, const float* __restrict__ resid,
         void* __restrict__ Cout, int M, int N, int K, int mode) {
    extern __shared__ char smc[];
    uint32_t sb = smem_u32(smc);
    int tid = threadIdx.x;
    int wid = tid >> 5, lane = tid & 31;
    int g = lane >> 2, t = lane & 3;
    int bm = blockIdx.y, bn = blockIdx.x;
    int wm0 = (wid & 1) * 64, wn0 = (wid >> 1) * 32;

    uint32_t a_off = (uint32_t)((wm0 + (lane & 15)) * 144 + ((lane >> 4) * 8) * 2);
    uint32_t b_off = (uint32_t)((wn0 + ((lane >> 4) << 3) + (lane & 7)) * 144 + (((lane >> 3) & 1) * 8) * 2);

    int r  = tid >> 1;
    int hh = (tid & 1) << 5;
    const __half* Ap = A + (size_t)(bm * 128 + r) * K + hh;
    const __half* Wp = W + (size_t)(bn * 128 + r) * K + hh;
    uint32_t smA_dst[3], smB_dst[3];
    #pragma unroll
    for (int s = 0; s < 3; s++) {
        smA_dst[s] = sb + ABUF(s) + r * 144 + hh * 2;
        smB_dst[s] = sb + BBUF(s) + r * 144 + hh * 2;
    }

    float acc[4][4][4] = {};
    int nc = K >> 6;

    #pragma unroll
    for (int i = 0; i < 4; i++) cp_async16(smA_dst[0] + i * 16, Ap + i * 8);
    #pragma unroll
    for (int i = 0; i < 4; i++) cp_async16(smB_dst[0] + i * 16, Wp + i * 8);
    CP_COMMIT();
    #pragma unroll
    for (int i = 0; i < 4; i++) cp_async16(smA_dst[1] + i * 16, Ap + 64 + i * 8);
    #pragma unroll
    for (int i = 0; i < 4; i++) cp_async16(smB_dst[1] + i * 16, Wp + 64 + i * 8);
    CP_COMMIT();

    for (int c = 0; c < nc; c++) {
        int s = c % 3;
        if (c + 1 < nc) { CP_WAIT(1); } else { CP_WAIT(0); }
        __syncthreads();
        if (c + 2 < nc) {
            int s2 = (c + 2) % 3;
            const __half* ap = Ap + (c + 2) * 64;
            const __half* wp = Wp + (c + 2) * 64;
            #pragma unroll
            for (int i = 0; i < 4; i++) cp_async16(smA_dst[s2] + i * 16, ap + i * 8);
            #pragma unroll
            for (int i = 0; i < 4; i++) cp_async16(smB_dst[s2] + i * 16, wp + i * 8);
            CP_COMMIT();
        }

        uint32_t Ab = sb + ABUF(s) + a_off;
        uint32_t Bb = sb + BBUF(s) + b_off;
        #pragma unroll
        for (int k0 = 0; k0 < 64; k0 += 16) {
            uint32_t af[4][4], bf[2][4];
            #pragma unroll
            for (int mt = 0; mt < 4; mt++) ldsm_x4(af[mt], Ab + mt * 2304 + k0 * 2);
            ldsm_x4(bf[0], Bb + k0 * 2);
            ldsm_x4(bf[1], Bb + 2304 + k0 * 2);
            #pragma unroll
            for (int mt = 0; mt < 4; mt++)
                #pragma unroll
                for (int nt = 0; nt < 4; nt++)
                    mma_f16(acc[mt][nt], af[mt], &bf[nt >> 1][(nt & 1) * 2]);
        }
    }

    #pragma unroll
    for (int mt = 0; mt < 4; mt++) {
        #pragma unroll
        for (int half_ = 0; half_ < 2; half_++) {
            int row = bm * 128 + wm0 + mt * 16 + g + half_ * 8;
            #pragma unroll
            for (int nt = 0; nt < 4; nt++) {
                int col = bn * 128 + wn0 + nt * 8 + 2 * t;
                float2 bv = *(const float2*)(bias + col);
                float vx = acc[mt][nt][2 * half_ + 0] + bv.x;
                float vy = acc[mt][nt][2 * half_ + 1] + bv.y;
                if (mode == 2) {
                    float2 rs = *(const float2*)(resid + (size_t)row * N + col);
                    vx += rs.x; vy += rs.y;
                    *(float2*)((float*)Cout + (size_t)row * N + col) = make_float2(vx, vy);
                } else {
                    if (mode == 1) {
                        vx = quickgelu(vx);
                        vy = quickgelu(vy);
                    }
                    __half* Co = (__half*)Cout + (size_t)row * N;
                    *(__half2*)(Co + col) = __floats2half2_rn(vx, vy);
                }
            }
        }
    }
}

// ---------------- LayerNorm: warp-per-row, 8 rows/block, shfl-only ----------------
__global__ void ln_kernel(const float* __restrict__ x, const float* __restrict__ g,
                          const float* __restrict__ b, __half* __restrict__ out) {
    int wid = threadIdx.x >> 5, lane = threadIdx.x & 31;
    int row = blockIdx.x * 8 + wid;
    const float* xr = x + (size_t)row * DIM;

    float4 v[6];
    float s = 0.f, ss = 0.f;
    #pragma unroll
    for (int j = 0; j < 6; j++) {
        v[j] = *(const float4*)(xr + (j * 32 + lane) * 4);
        s  += v[j].x + v[j].y + v[j].z + v[j].w;
        ss += v[j].x * v[j].x + v[j].y * v[j].y + v[j].z * v[j].z + v[j].w * v[j].w;
    }
    #pragma unroll
    for (int o = 16; o > 0; o >>= 1) {
        s  += __shfl_xor_sync(0xffffffffu, s, o);
        ss += __shfl_xor_sync(0xffffffffu, ss, o);
    }
    float mean = s * (1.f / DIM);
    float var  = ss * (1.f / DIM) - mean * mean;
    float rstd = rsqrtf(var + 1e-5f);

    __half* orow = out + (size_t)row * DIM;
    #pragma unroll
    for (int j = 0; j < 6; j++) {
        int idx = (j * 32 + lane) * 4;
        float4 gv = *(const float4*)(g + idx);
        float4 bv = *(const float4*)(b + idx);
        __half2 h0 = __floats2half2_rn((v[j].x - mean) * rstd * gv.x + bv.x,
                                       (v[j].y - mean) * rstd * gv.y + bv.y);
        __half2 h1 = __floats2half2_rn((v[j].z - mean) * rstd * gv.z + bv.z,
                                       (v[j].w - mean) * rstd * gv.w + bv.w);
        *(uint2*)(orow + idx) = make_uint2(*(uint32_t*)&h0, *(uint32_t*)&h1);
    }
}

// ---------------- FlashAttention-2 (R12 shape): Q hoist, fused softmax/PV, 2-buffer ----
#define FKV(i) (9216 + (i) * 9216)
#define FATT_BYTES ((9216 + 2 * 9216) * 2)  // 55296
#define SM_C 0.18033688f                     // 0.125 * log2(e)

__global__ void __launch_bounds__(256, 2)
attn_kernel(const __half* __restrict__ qkv, const float* __restrict__ prompt,
            __half* __restrict__ out) {
    extern __shared__ __half sh[];
    __half* Qs = sh;

    uint32_t sbase = smem_u32(sh);
    int qt = blockIdx.x, h = blockIdx.y, b = blockIdx.z;
    int tid = threadIdx.x;
    int wid = tid >> 5, lane = tid & 31;
    int g = lane >> 2, t = lane & 3;
    int q0 = wid * 16;

    uint32_t aq_off = (uint32_t)((q0 + (lane & 15)) * 144 + ((lane >> 4) * 8) * 2);
    uint32_t bk_off = (uint32_t)((((lane >> 4) << 3) + (lane & 7)) * 144 + (((lane >> 3) & 1) * 8) * 2);
    uint32_t bv_off = (uint32_t)((lane & 15) * 144 + ((lane >> 4) << 3) * 2);

    // --- Q tile (128 rows) ---
    {
        int q = tid >> 1, ch = tid & 1;
        int n = qt * 128 + q;
        const __half* src = qkv + (size_t)(b * SEQ + n) * (3 * DIM) + h * HDIM + ch * 32;
        *(uint4*)(Qs + q * 72 + ch * 32)      = *(const uint4*)(src);
        *(uint4*)(Qs + q * 72 + ch * 32 + 8)  = *(const uint4*)(src + 8);
        *(uint4*)(Qs + q * 72 + ch * 32 + 16) = *(const uint4*)(src + 16);
        *(uint4*)(Qs + q * 72 + ch * 32 + 24) = *(const uint4*)(src + 24);
    }

    // --- tile 0 K/V: synchronous fill into buf 0 (handles prompt conversion) ---
    {
        int key = tid & 63, ch = tid >> 6;
        int tensor = ch >> 1, c2 = ch & 1;
        __half* dst = sh + FKV(0) + tensor * 4608 + key * 72 + c2 * 32;
        if (key >= PLEN) {
            const __half* src = qkv + (size_t)(b * SEQ + (key - PLEN)) * (3 * DIM)
                                + (1 + tensor) * DIM + h * HDIM + c2 * 32;
            *(uint4*)(dst)      = *(const uint4*)(src);
            *(uint4*)(dst + 8)  = *(const uint4*)(src + 8);
            *(uint4*)(dst + 16) = *(const uint4*)(src + 16);
            *(uint4*)(dst + 24) = *(const uint4*)(src + 24);
        } else {
            const float* src = prompt + ((((size_t)b * 2 + tensor) * PLEN + key) * NH + h) * HDIM + c2 * 32;
            #pragma unroll
            for (int ii = 0; ii < 16; ii++) {
                float2 v = *(const float2*)(src + ii * 2);
                *(__half2*)(dst + ii * 2) = __floats2half2_rn(v.x, v.y);
            }
        }
    }
    __syncthreads();                      // Q + tile0 K/V visible

    // --- hoist Q fragments (loop-invariant): 16 regs ---
    uint32_t qf[4][4];
    #pragma unroll
    for (int i = 0; i < 4; i++) ldsm_x4(qf[i], sbase + aq_off + i * 32);

    float m0 = -1e30f, m1 = -1e30f, l0 = 0.f, l1 = 0.f;   // m in log2-scaled domain
    float acc_o[8][4] = {};

    int pkey = tid & 63, pch = tid >> 6;
    int ptensor = pch >> 1, pc2 = pch & 1;

    // ================= main loop: tiles 0..15, no masking =================
    for (int kt = 0; kt < 16; kt++) {
        int bb = kt & 1;
        if (kt >= 1) { CP_WAIT(0); __syncthreads(); }

        {   // prefetch tile kt+1 (zfill covers the tile-16 tail)
            int kg = (kt + 1) * 64 + pkey;
            int kgc = kg < KEYS ? kg : KEYS - 1;
            int sz = kg < KEYS ? 16 : 0;
            const __half* src = qkv + (size_t)(b * SEQ + (kgc - PLEN)) * (3 * DIM)
                                + (1 + ptensor) * DIM + h * HDIM + pc2 * 32;
            uint32_t dst = sbase + (uint32_t)(FKV(bb ^ 1) + ptensor * 4608 + pkey * 72 + pc2 * 32) * 2;
            #pragma unroll
            for (int i = 0; i < 4; i++) cp_async16_z(dst + i * 16, src + i * 8, sz);
            CP_COMMIT();
        }

        uint32_t kbase_b = sbase + (uint32_t)FKV(bb) * 2;
        uint32_t vbase_b = kbase_b + 4608 * 2;

        // --- S = Q @ K^T ---
        float s4[8][4] = {};
        #pragma unroll
        for (int k0i = 0; k0i < 4; k0i++) {
            uint32_t bf[4][4];
            #pragma unroll
            for (int j = 0; j < 4; j++)
                ldsm_x4(bf[j], kbase_b + bk_off + j * 16 * 144 + k0i * 32);
            #pragma unroll
            for (int nt = 0; nt < 8; nt++)
                mma_f16(s4[nt], qf[k0i], &bf[nt >> 1][(nt & 1) * 2]);
        }

        // --- softmax pass A: max / rescale ---
        float tm0 = -1e30f, tm1 = -1e30f;
        #pragma unroll
        for (int nt = 0; nt < 8; nt++) {
            tm0 = fmaxf(tm0, fmaxf(s4[nt][0], s4[nt][1]));
            tm1 = fmaxf(tm1, fmaxf(s4[nt][2], s4[nt][3]));
        }
        tm0 = fmaxf(tm0, __shfl_xor_sync(0xffffffffu, tm0, 1));
        tm0 = fmaxf(tm0, __shfl_xor_sync(0xffffffffu, tm0, 2));
        tm1 = fmaxf(tm1, __shfl_xor_sync(0xffffffffu, tm1, 1));
        tm1 = fmaxf(tm1, __shfl_xor_sync(0xffffffffu, tm1, 2));
        float mn0 = fmaxf(m0, tm0 * SM_C);
        float mn1 = fmaxf(m1, tm1 * SM_C);
        float a0 = ex2f(m0 - mn0), a1 = ex2f(m1 - mn1);
        m0 = mn0; m1 = mn1;
        #pragma unroll
        for (int nt = 0; nt < 8; nt++) {
            acc_o[nt][0] *= a0; acc_o[nt][1] *= a0;
            acc_o[nt][2] *= a1; acc_o[nt][3] *= a1;
        }

        // --- pass B: per 16-key chunk, P-halves + PV immediately ---
        float ls0 = 0.f, ls1 = 0.f;
        #pragma unroll
        for (int j = 0; j < 4; j++) {
            uint32_t af[4];
            #pragma unroll
            for (int u = 0; u < 2; u++) {
                int nt = 2 * j + u;
                float p0 = ex2f(fmaf(s4[nt][0], SM_C, -mn0));
                float p1 = ex2f(fmaf(s4[nt][1], SM_C, -mn0));
                float p2 = ex2f(fmaf(s4[nt][2], SM_C, -mn1));
                float p3 = ex2f(fmaf(s4[nt][3], SM_C, -mn1));
                ls0 += p0 + p1; ls1 += p2 + p3;
                __half2 h01 = __floats2half2_rn(p0, p1);
                __half2 h23 = __floats2half2_rn(p2, p3);
                af[2 * u + 0] = *(uint32_t*)&h01;
                af[2 * u + 1] = *(uint32_t*)&h23;
            }
            uint32_t bf[4][4];
            #pragma unroll
            for (int dj = 0; dj < 4; dj++)
                ldsm_x4_t(bf[dj], vbase_b + bv_off + j * 16 * 144 + dj * 16 * 2);
            #pragma unroll
            for (int nt = 0; nt < 8; nt++)
                mma_f16(acc_o[nt], af, &bf[nt >> 1][(nt & 1) * 2]);
        }
        ls0 += __shfl_xor_sync(0xffffffffu, ls0, 1);
        ls0 += __shfl_xor_sync(0xffffffffu, ls0, 2);
        ls1 += __shfl_xor_sync(0xffffffffu, ls1, 1);
        ls1 += __shfl_xor_sync(0xffffffffu, ls1, 2);
        l0 = l0 * a0 + ls0;
        l1 = l1 * a1 + ls1;
    }

    // ================= last tile (kt=16): keys 1024..1039, quarter work =================
    {
        CP_WAIT(0);
        __syncthreads();
        uint32_t kbase_b = sbase + (uint32_t)FKV(0) * 2;   // 16 & 1 == 0
        uint32_t vbase_b = kbase_b + 4608 * 2;

        float s4[2][4] = {};
        #pragma unroll
        for (int k0i = 0; k0i < 4; k0i++) {
            uint32_t bf[4];
            ldsm_x4(bf, kbase_b + bk_off + k0i * 32);
            mma_f16(s4[0], qf[k0i], &bf[0]);
            mma_f16(s4[1], qf[k0i], &bf[2]);
        }
        float tm0 = fmaxf(fmaxf(s4[0][0], s4[0][1]), fmaxf(s4[1][0], s4[1][1]));
        float tm1 = fmaxf(fmaxf(s4[0][2], s4[0][3]), fmaxf(s4[1][2], s4[1][3]));
        tm0 = fmaxf(tm0, __shfl_xor_sync(0xffffffffu, tm0, 1));
        tm0 = fmaxf(tm0, __shfl_xor_sync(0xffffffffu, tm0, 2));
        tm1 = fmaxf(tm1, __shfl_xor_sync(0xffffffffu, tm1, 1));
        tm1 = fmaxf(tm1, __shfl_xor_sync(0xffffffffu, tm1, 2));
        float mn0 = fmaxf(m0, tm0 * SM_C);
        float mn1 = fmaxf(m1, tm1 * SM_C);
        float a0 = ex2f(m0 - mn0), a1 = ex2f(m1 - mn1);
        #pragma unroll
        for (int nt = 0; nt < 8; nt++) {
            acc_o[nt][0] *= a0; acc_o[nt][1] *= a0;
            acc_o[nt][2] *= a1; acc_o[nt][3] *= a1;
        }

        float ls0 = 0.f, ls1 = 0.f;
        uint32_t af[4];
        #pragma unroll
        for (int u = 0; u < 2; u++) {
            float p0 = ex2f(fmaf(s4[u][0], SM_C, -mn0));
            float p1 = ex2f(fmaf(s4[u][1], SM_C, -mn0));
            float p2 = ex2f(fmaf(s4[u][2], SM_C, -mn1));
            float p3 = ex2f(fmaf(s4[u][3], SM_C, -mn1));
            ls0 += p0 + p1; ls1 += p2 + p3;
            __half2 h01 = __floats2half2_rn(p0, p1);
            __half2 h23 = __floats2half2_rn(p2, p3);
            af[2 * u + 0] = *(uint32_t*)&h01;
            af[2 * u + 1] = *(uint32_t*)&h23;
        }
        uint32_t bf[4][4];
        #pragma unroll
        for (int dj = 0; dj < 4; dj++)
            ldsm_x4_t(bf[dj], vbase_b + bv_off + dj * 16 * 2);
        #pragma unroll
        for (int nt = 0; nt < 8; nt++)
            mma_f16(acc_o[nt], af, &bf[nt >> 1][(nt & 1) * 2]);

        ls0 += __shfl_xor_sync(0xffffffffu, ls0, 1);
        ls0 += __shfl_xor_sync(0xffffffffu, ls0, 2);
        ls1 += __shfl_xor_sync(0xffffffffu, ls1, 1);
        ls1 += __shfl_xor_sync(0xffffffffu, ls1, 2);
        l0 = l0 * a0 + ls0;
        l1 = l1 * a1 + ls1;
    }

    // --- finalize ---
    float li0 = 1.f / l0, li1 = 1.f / l1;
    int nrow0 = qt * 128 + q0 + g;
    __half* o0 = out + (size_t)(b * SEQ + nrow0) * DIM + h * HDIM;
    __half* o1 = out + (size_t)(b * SEQ + nrow0 + 8) * DIM + h * HDIM;
    #pragma unroll
    for (int nt = 0; nt < 8; nt++) {
        int col = nt * 8 + 2 * t;
        *(__half2*)(o0 + col) = __floats2half2_rn(acc_o[nt][0] * li0, acc_o[nt][1] * li0);
        *(__half2*)(o1 + col) = __floats2half2_rn(acc_o[nt][2] * li1, acc_o[nt][3] * li1);
    }
}

// ---------------- launch ----------------
extern "C" void kernel_launch(void* const* d_in, const int* in_sizes, int n_in,
                              void* d_out, int out_size) {
    const float* x      = (const float*)d_in[0];
    const float* prompt = (const float*)d_in[1];
    const float* qkv_w  = (const float*)d_in[2];
    const float* qkv_b  = (const float*)d_in[3];
    const float* out_w  = (const float*)d_in[4];
    const float* out_b  = (const float*)d_in[5];
    const float* ln1_g  = (const float*)d_in[6];
    const float* ln1_b  = (const float*)d_in[7];
    const float* ln2_g  = (const float*)d_in[8];
    const float* ln2_b  = (const float*)d_in[9];
    const float* fc1_w  = (const float*)d_in[10];
    const float* fc1_b  = (const float*)d_in[11];
    const float* fc2_w  = (const float*)d_in[12];
    const float* fc2_b  = (const float*)d_in[13];
    float* out = (float*)d_out;

    __half *h, *qkv, *attn, *ff, *w;
    float *xr;
    cudaGetSymbolAddress((void**)&h,    g_h);
    cudaGetSymbolAddress((void**)&qkv,  g_qkv);
    cudaGetSymbolAddress((void**)&attn, g_attn);
    cudaGetSymbolAddress((void**)&xr,   g_xr);
    cudaGetSymbolAddress((void**)&ff,   g_ff);
    cudaGetSymbolAddress((void**)&w,    g_w);

    __half* wq  = w + WQ_OFF;
    __half* wo  = w + WO_OFF;
    __half* wf1 = w + WF1_OFF;
    __half* wf2 = w + WF2_OFF;

    cudaFuncSetAttribute(attn_kernel, cudaFuncAttributeMaxDynamicSharedMemorySize, FATT_BYTES);
    cudaFuncSetAttribute(mma_gemm, cudaFuncAttributeMaxDynamicSharedMemorySize, GSM_BYTES);

    // 0) weights -> fp16
    cvt_w_all<<<(int)((WTOTAL / 4 + 255) / 256), 256>>>(qkv_w, out_w, fc1_w, fc2_w, w);

    // 1) h = LN1(x)
    ln_kernel<<<ROWS / 8, 256>>>(x, ln1_g, ln1_b, h);
    // 2) qkv = h @ qkv_w^T + qkv_b
    mma_gemm<<<dim3(3 * DIM / 128, ROWS / 128), 256, GSM_BYTES>>>(h, wq, qkv_b, nullptr, qkv,
                                                                  ROWS, 3 * DIM, DIM, 0);
    // 3) attention
    attn_kernel<<<dim3(SEQ / 128, NH, BSZ), 256, FATT_BYTES>>>(qkv, prompt, attn);
    // 4) xr = x + attn @ out_w^T + out_b
    mma_gemm<<<dim3(DIM / 128, ROWS / 128), 256, GSM_BYTES>>>(attn, wo, out_b, x, xr,
                                                              ROWS, DIM, DIM, 2);
    // 5) h = LN2(xr)
    ln_kernel<<<ROWS / 8, 256>>>(xr, ln2_g, ln2_b, h);
    // 6) ff = quickgelu(h @ fc1_w^T + fc1_b)
    mma_gemm<<<dim3(FFD / 128, ROWS / 128), 256, GSM_BYTES>>>(h, wf1, fc1_b, nullptr, ff,
                                                              ROWS, FFD, DIM, 1);
    // 7) out = xr + ff @ fc2_w^T + fc2_b
    mma_gemm<<<dim3(DIM / 128, ROWS / 128), 256, GSM_BYTES>>>(ff, wf2, fc2_b, xr, out,
                                                              ROWS, DIM, FFD, 2);
}